// round 16
// baseline (speedup 1.0000x reference)
#include <cuda_runtime.h>
#include <cuda_fp16.h>
#include <cstdint>

#define BT 2048
#define NF 128
#define CC 256

// Device globals (no allocations)
__device__ uint32_t g_WqkPh[CC * CC / 2];    // pair-interleaved half2 B: n<128 Wq, else Wk
__device__ uint32_t g_WctPh[CC * CC / 2];    // pair-interleaved half2 B: Wc = Wg@Wv
__device__ float    g_bc[CC];                // Wg @ bv + bg
__device__ float    g_eqb[NF * 128];         // ee @ Wq^T + bq   [r][j]
__device__ float    g_ekb[NF * 128];         // ee @ Wk^T + bk   [r][j]

__device__ __forceinline__ uint32_t pk(float a, float b) {
    __half2 h = __floats2half2_rn(a, b);
    return *(uint32_t*)&h;
}
__device__ __forceinline__ uint32_t smem_u32(const void* p) {
    uint32_t a;
    asm("{ .reg .u64 t; cvta.to.shared.u64 t, %1; cvt.u32.u64 %0, t; }" : "=r"(a) : "l"(p));
    return a;
}
#define CP16(d, s) asm volatile("cp.async.ca.shared.global [%0], [%1], 16;" :: "r"(d), "l"(s) : "memory")
#define CP_COMMIT() asm volatile("cp.async.commit_group;" ::: "memory")
#define CP_WAIT2()  asm volatile("cp.async.wait_group 2;" ::: "memory")

__device__ __forceinline__ void mma16(float c[4], uint4 a, uint32_t b0, uint32_t b1) {
    asm volatile(
        "mma.sync.aligned.m16n8k16.row.col.f32.f16.f16.f32 "
        "{%0,%1,%2,%3},{%4,%5,%6,%7},{%8,%9},{%0,%1,%2,%3};"
        : "+f"(c[0]), "+f"(c[1]), "+f"(c[2]), "+f"(c[3])
        : "r"(a.x), "r"(a.y), "r"(a.z), "r"(a.w), "r"(b0), "r"(b1));
}

// Pair-interleaved B-pack word index: two adjacent 8-col fragments share a 16B slot.
// word = ((s*NP2 + gp2)*32 + g*4 + t)*4 + go*2 + hi   (NP2 = N/16)
__device__ __forceinline__ int bw2(int NP2, int k, int n) {
    int s = k >> 4, kk = k & 15, t = (kk & 7) >> 1, hi = kk >> 3;
    int gp = n >> 3, gp2 = gp >> 1, go = gp & 1, g = n & 7;
    return ((s * NP2 + gp2) * 32 + g * 4 + t) * 4 + go * 2 + hi;
}

// One k16 step, uint4 B loads: warp tile 32 x (NT2*16).
template <int NT2>
__device__ __forceinline__ void step16w(float (&acc)[2][8][4], const uint32_t* __restrict__ Aw,
                                        const uint32_t* __restrict__ Bw) {
    uint4 af[2];
#pragma unroll
    for (int mt = 0; mt < 2; mt++) af[mt] = *(const uint4*)(Aw + mt * 128);
#pragma unroll
    for (int nt2 = 0; nt2 < NT2; nt2++) {
        uint4 bf = *(const uint4*)(Bw + nt2 * 128);
#pragma unroll
        for (int mt = 0; mt < 2; mt++) {
            mma16(acc[mt][2 * nt2],     af[mt], bf.x, bf.y);
            mma16(acc[mt][2 * nt2 + 1], af[mt], bf.z, bf.w);
        }
    }
}

// ---------------- prep 1: Wct pack, Wqk pack, bc ----------------
__global__ void prep_all(const float* __restrict__ Wq, const float* __restrict__ Wk,
                         const float* __restrict__ Wg, const float* __restrict__ Wv,
                         const float* __restrict__ bv, const float* __restrict__ bg)
{
    __shared__ float sWg[4][256];
    __shared__ float sWct[4][260];
    __shared__ float part[4][8];
    const int bi = blockIdx.x;      // 0..63, owns Wct rows i0..i0+3
    const int j = threadIdx.x;      // 0..255
    const int i0 = bi * 4;
    const int w8 = j >> 5, lane = j & 31;

#pragma unroll
    for (int r = 0; r < 4; r++) sWg[r][j] = Wg[(i0 + r) * 256 + j];
    __syncthreads();

    float acc[4] = {0.f, 0.f, 0.f, 0.f};
#pragma unroll 4
    for (int k = 0; k < 256; k++) {
        float wv = Wv[k * 256 + j];
#pragma unroll
        for (int r = 0; r < 4; r++) acc[r] = fmaf(sWg[r][k], wv, acc[r]);
    }
#pragma unroll
    for (int r = 0; r < 4; r++) sWct[r][j] = acc[r];

#pragma unroll
    for (int r = 0; r < 4; r++) {
        float v = sWg[r][j] * bv[j];
#pragma unroll
        for (int off = 16; off; off >>= 1) v += __shfl_xor_sync(0xffffffffu, v, off);
        if (lane == 0) part[r][w8] = v;
    }
    __syncthreads();

    if (j < 4) {
        float s = 0.f;
#pragma unroll
        for (int ww = 0; ww < 8; ww++) s += part[j][ww];
        g_bc[i0 + j] = s + bg[i0 + j];
    }
#pragma unroll
    for (int q = 0; q < 2; q++) {
        int idx = j * 2 + q;
        int nl = idx >> 7, kp = idx & 127;
        g_WctPh[bw2(16, 2 * kp, i0 + nl)] = pk(sWct[nl][2 * kp], sWct[nl][2 * kp + 1]);
    }
#pragma unroll
    for (int q = 0; q < 2; q++) {
        int p2 = bi * 512 + j * 2 + q;
        int kp = p2 >> 8, n = p2 & 255;
        float q0, q1;
        if (n < 128) { q0 = Wq[n * 256 + 2 * kp]; q1 = Wq[n * 256 + 2 * kp + 1]; }
        else         { q0 = Wk[(n - 128) * 256 + 2 * kp]; q1 = Wk[(n - 128) * 256 + 2 * kp + 1]; }
        g_WqkPh[bw2(16, 2 * kp, n)] = pk(q0, q1);
    }
}

// ---------------- prep 2: eqb = ee@Wq^T + bq, ekb = ee@Wk^T + bk ----------------
__global__ void prep_eqk(const float* __restrict__ ee, const float* __restrict__ Wq,
                         const float* __restrict__ Wk, const float* __restrict__ bq,
                         const float* __restrict__ bk)
{
    __shared__ float se[256];
    const int n = blockIdx.x, j = threadIdx.x;
    se[j] = ee[n * 256 + j];
    __syncthreads();
    const float* Wr = (j < 128) ? (Wq + j * 256) : (Wk + (j - 128) * 256);
    float a0 = 0.f, a1 = 0.f, a2 = 0.f, a3 = 0.f;
#pragma unroll 8
    for (int k = 0; k < 256; k += 4) {
        a0 = fmaf(se[k + 0], Wr[k + 0], a0);
        a1 = fmaf(se[k + 1], Wr[k + 1], a1);
        a2 = fmaf(se[k + 2], Wr[k + 2], a2);
        a3 = fmaf(se[k + 3], Wr[k + 3], a3);
    }
    float dot = (a0 + a1) + (a2 + a3);
    if (j < 128) g_eqb[n * 128 + j] = dot + bq[j];
    else         g_ekb[n * 128 + (j - 128)] = dot + bk[j - 128];
}

// SMEM word map: scr[1024] | A1[16384] (xA -> Q|Kt -> attn|Kt -> ax) | XB[16384] | BB[16384]
constexpr int OFF_SCR = 0;
constexpr int OFF_A   = 1024;
constexpr int OFF_XB  = OFF_A + 16384;
constexpr int OFF_BB  = OFF_XB + 16384;
constexpr int SMEM_W  = OFF_BB + 16384;      // 50176 words
constexpr int SMEM_BYTES = SMEM_W * 4;       // 200704 B

__global__ void __launch_bounds__(512, 1)
fused_kernel(const float* __restrict__ x, const float* __restrict__ adj,
             const float* __restrict__ alpha_p,
             const float* __restrict__ gamma, const float* __restrict__ beta,
             float* __restrict__ out)
{
    extern __shared__ uint32_t smw[];
    float*    scr = (float*)(smw + OFF_SCR);
    uint32_t* A1  = smw + OFF_A;               // xA(S16) / Q+Kt / attn+Kt / ax(S16)
    uint32_t* XB  = smw + OFF_XB;              // persistent x B-pack (phase 3)
    uint32_t* BB  = smw + OFF_BB;
    const uint32_t bbu = smem_u32(smw + OFF_BB);

    const int tid = threadIdx.x;
    const int w = tid >> 5, lane = tid & 31;
    const int g = lane >> 2, t = lane & 3;
    const int wm = w >> 2, wn = w & 3;          // 4 x 4 warp grid
    const int mrow = wm * 32;
    const int ncol = wn * 64;                   // phases 1,3,4 (N=256)
    const int ncol2 = wn * 32;                  // phase 2 (N=128)
    const int b = blockIdx.x;
    const float* xb = x + (size_t)b * (NF * CC);

    float acc[2][8][4];

#define ISSUE_W2(cc, gW) do { \
    if ((cc) < 8) { \
        uint32_t d = bbu + (((cc) & 3) * 4096 + tid * 8) * 4; \
        const uint32_t* s_ = (gW) + (cc) * 4096 + tid * 8; \
        CP16(d, s_); CP16(d + 16, s_ + 4); \
    } \
    CP_COMMIT(); \
} while (0)

#define ZACC() do { \
    _Pragma("unroll") for (int mt = 0; mt < 2; mt++) \
    _Pragma("unroll") for (int nt = 0; nt < 8; nt++) \
    _Pragma("unroll") for (int e = 0; e < 4; e++) acc[mt][nt][e] = 0.f; \
} while (0)

    ISSUE_W2(0, g_WqkPh);
    ISSUE_W2(1, g_WqkPh);

    // ===== stage x A-pack (S=16), fragment-owner conflict-free uint4 =====
#pragma unroll
    for (int it = 0; it < 8; it++) {
        int u = it * 16 + w;
        int slab = u >> 5, s = (u >> 1) & 15, mt = u & 1;
        int r0 = slab * 32 + mt * 16 + g;
        int k0 = s * 16 + 2 * t;
        const float* px = xb + r0 * 256 + k0;
        float2 a0 = __ldg((const float2*)px);
        float2 a1 = __ldg((const float2*)(px + 8 * 256));
        float2 a2 = __ldg((const float2*)(px + 8));
        float2 a3 = __ldg((const float2*)(px + 8 * 256 + 8));
        uint4 v;
        v.x = pk(a0.x, a0.y); v.y = pk(a1.x, a1.y);
        v.z = pk(a2.x, a2.y); v.w = pk(a3.x, a3.y);
        ((uint4*)A1)[((slab * 16 + s) * 2 + mt) * 32 + lane] = v;
    }

    // ===== stage persistent x B-pack (pair-interleaved), conflict-free uint4 =====
#pragma unroll
    for (int it = 0; it < 8; it++) {
        int u = it * 16 + w;
        int s = u >> 4, gp2 = u & 15;
        int n_e = gp2 * 16 + g;
        const float* p = xb + (s * 16 + 2 * t) * 256;
        float e0 = __ldg(p + n_e),           e1 = __ldg(p + 256 + n_e);
        float e8 = __ldg(p + 8 * 256 + n_e), e9 = __ldg(p + 9 * 256 + n_e);
        float o0 = __ldg(p + n_e + 8),           o1 = __ldg(p + 256 + n_e + 8);
        float o8 = __ldg(p + 8 * 256 + n_e + 8), o9 = __ldg(p + 9 * 256 + n_e + 8);
        uint4 v;
        v.x = pk(e0, e1); v.y = pk(e8, e9);
        v.z = pk(o0, o1); v.w = pk(o8, o9);
        ((uint4*)XB)[(s * 16 + gp2) * 32 + lane] = v;
    }

    // ===== Phase 1: [Q|K] = x @ Wqk^T  (8 double-ksteps) =====
    ZACC();
    for (int cc = 0; cc < 8; cc++) {
        ISSUE_W2(cc + 2, g_WqkPh);
        CP_WAIT2();
        __syncthreads();
#pragma unroll
        for (int sl = 0; sl < 2; sl++)
            step16w<4>(acc, A1 + wm * 4096 + (2 * cc + sl) * 256 + lane * 4,
                       BB + (cc & 3) * 4096 + sl * 2048 + wn * 512 + lane * 4);
    }
    __syncthreads();   // all xA reads done before Q/Kt overwrite A1

    // epilogue: Q-pack (wn<2) / Kt-pack (wn>=2), row-dependent ee-fold bias, uint4
    if (wn < 2) {
#pragma unroll
        for (int np = 0; np < 4; np++) {
            int n0 = ncol + np * 16 + 2 * t;
#pragma unroll
            for (int mt = 0; mt < 2; mt++) {
                int r0 = mrow + mt * 16 + g;
                float2 e00 = __ldg((const float2*)&g_eqb[r0 * 128 + n0]);
                float2 e10 = __ldg((const float2*)&g_eqb[(r0 + 8) * 128 + n0]);
                float2 e01 = __ldg((const float2*)&g_eqb[r0 * 128 + n0 + 8]);
                float2 e11 = __ldg((const float2*)&g_eqb[(r0 + 8) * 128 + n0 + 8]);
                uint4 v;
                v.x = pk(acc[mt][2 * np][0] + e00.x, acc[mt][2 * np][1] + e00.y);
                v.y = pk(acc[mt][2 * np][2] + e10.x, acc[mt][2 * np][3] + e10.y);
                v.z = pk(acc[mt][2 * np + 1][0] + e01.x, acc[mt][2 * np + 1][1] + e01.y);
                v.w = pk(acc[mt][2 * np + 1][2] + e11.x, acc[mt][2 * np + 1][3] + e11.y);
                ((uint4*)A1)[((wm * 8 + wn * 4 + np) * 2 + mt) * 32 + lane] = v;
            }
        }
    } else {
#pragma unroll
        for (int np = 0; np < 4; np++) {
            int ck0 = (wn - 2) * 64 + np * 16 + 2 * t;
            int sb = (wn - 2) * 4 + np;
#pragma unroll
            for (int mt = 0; mt < 2; mt++) {
                int r0 = mrow + mt * 16 + g;
                float2 k00 = __ldg((const float2*)&g_ekb[r0 * 128 + ck0]);
                float2 k01 = __ldg((const float2*)&g_ekb[r0 * 128 + ck0 + 8]);
                float2 k10 = __ldg((const float2*)&g_ekb[(r0 + 8) * 128 + ck0]);
                float2 k11 = __ldg((const float2*)&g_ekb[(r0 + 8) * 128 + ck0 + 8]);
                uint4 v;
                v.x = pk(acc[mt][2 * np][0] + k00.x, acc[mt][2 * np][1] + k00.y);
                v.y = pk(acc[mt][2 * np + 1][0] + k01.x, acc[mt][2 * np + 1][1] + k01.y);
                v.z = pk(acc[mt][2 * np][2] + k10.x, acc[mt][2 * np][3] + k10.y);
                v.w = pk(acc[mt][2 * np + 1][2] + k11.x, acc[mt][2 * np + 1][3] + k11.y);
                ((uint4*)(A1 + 8192))[(sb * 8 + wm * 2 + mt) * 32 + lane] = v;
            }
        }
    }
    __syncthreads();

    // ===== Phase 2: scores = Q @ K^T  (8 ksteps) =====
    ZACC();
#pragma unroll
    for (int s = 0; s < 8; s++)
        step16w<2>(acc, A1 + wm * 2048 + s * 256 + lane * 4,
                   A1 + 8192 + s * 1024 + wn * 256 + lane * 4);

    // ===== softmax (no max pass) -> attn-pack uint4 =====
    {
        const float fa = __ldg(alpha_p);
        const float invs = 0.08838834764831845f;
#pragma unroll
        for (int mt = 0; mt < 2; mt++)
#pragma unroll
            for (int h = 0; h < 2; h++) {
                const int r = mrow + mt * 16 + g + h * 8;
                float s = 0.f;
#pragma unroll
                for (int nt = 0; nt < 4; nt++) {
                    const int col = ncol2 + nt * 8 + 2 * t;
                    float2 av = __ldg((const float2*)&adj[r * 128 + col]);
                    float p0 = __expf(acc[mt][nt][h * 2 + 0] * invs + fa * fmaxf(av.x, 0.f));
                    float p1 = __expf(acc[mt][nt][h * 2 + 1] * invs + fa * fmaxf(av.y, 0.f));
                    acc[mt][nt][h * 2 + 0] = p0;
                    acc[mt][nt][h * 2 + 1] = p1;
                    s += p0 + p1;
                }
                s += __shfl_xor_sync(0xffffffffu, s, 1);
                s += __shfl_xor_sync(0xffffffffu, s, 2);
                scr[r * 4 + wn] = s;
            }
        __syncthreads();
#pragma unroll
        for (int mt = 0; mt < 2; mt++) {
            const int r0 = mrow + mt * 16 + g;
            const float* s0 = &scr[r0 * 4];
            const float* s1 = &scr[(r0 + 8) * 4];
            const float inv0 = 1.f / (s0[0] + s0[1] + s0[2] + s0[3]);
            const float inv1 = 1.f / (s1[0] + s1[1] + s1[2] + s1[3]);
#pragma unroll
            for (int np = 0; np < 2; np++) {
                uint4 v;
                v.x = pk(acc[mt][2 * np][0] * inv0, acc[mt][2 * np][1] * inv0);
                v.y = pk(acc[mt][2 * np][2] * inv1, acc[mt][2 * np][3] * inv1);
                v.z = pk(acc[mt][2 * np + 1][0] * inv0, acc[mt][2 * np + 1][1] * inv0);
                v.w = pk(acc[mt][2 * np + 1][2] * inv1, acc[mt][2 * np + 1][3] * inv1);
                ((uint4*)A1)[((wm * 8 + wn * 2 + np) * 2 + mt) * 32 + lane] = v;
            }
        }
    }
    __syncthreads();   // attn visible before phase-3 reads

    // ===== Phase 3: ax = attn @ x  (8 straight ksteps, B = persistent XB, no barriers) =====
    ZACC();
#pragma unroll
    for (int s = 0; s < 8; s++)
        step16w<4>(acc, A1 + wm * 2048 + s * 256 + lane * 4,
                   XB + s * 2048 + wn * 512 + lane * 4);

    // prefetch first two weight double-chunks of phase 4 (BB long dead)
    ISSUE_W2(0, g_WctPh);
    ISSUE_W2(1, g_WctPh);

    // epilogue: ax-pack (S=16) uint4 (attn/Kt dead)
#pragma unroll
    for (int np = 0; np < 4; np++)
#pragma unroll
        for (int mt = 0; mt < 2; mt++) {
            uint4 v;
            v.x = pk(acc[mt][2 * np][0], acc[mt][2 * np][1]);
            v.y = pk(acc[mt][2 * np][2], acc[mt][2 * np][3]);
            v.z = pk(acc[mt][2 * np + 1][0], acc[mt][2 * np + 1][1]);
            v.w = pk(acc[mt][2 * np + 1][2], acc[mt][2 * np + 1][3]);
            ((uint4*)A1)[((wm * 16 + wn * 4 + np) * 2 + mt) * 32 + lane] = v;
        }
    __syncthreads();

    // ===== Phase 4: z = ax @ Wc^T  (8 double-ksteps) =====
    ZACC();
    for (int cc = 0; cc < 8; cc++) {
        ISSUE_W2(cc + 2, g_WctPh);
        CP_WAIT2();
        __syncthreads();
#pragma unroll
        for (int sl = 0; sl < 2; sl++)
            step16w<4>(acc, A1 + wm * 4096 + (2 * cc + sl) * 256 + lane * 4,
                       BB + (cc & 3) * 4096 + sl * 2048 + wn * 512 + lane * 4);
    }

    // ===== LN epilogue: h = relu(z + bc) + x; LayerNorm over C; store =====
#pragma unroll
    for (int mt = 0; mt < 2; mt++)
#pragma unroll
        for (int h = 0; h < 2; h++) {
            const int r = mrow + mt * 16 + g + h * 8;
            float s1 = 0.f, s2 = 0.f;
#pragma unroll
            for (int nt = 0; nt < 8; nt++) {
                const int n = ncol + nt * 8 + 2 * t;
                float2 bc2 = __ldg((const float2*)&g_bc[n]);
                float2 xv = __ldg((const float2*)&xb[r * 256 + n]);
                float h0 = fmaxf(acc[mt][nt][h * 2 + 0] + bc2.x, 0.f) + xv.x;
                float h1 = fmaxf(acc[mt][nt][h * 2 + 1] + bc2.y, 0.f) + xv.y;
                acc[mt][nt][h * 2 + 0] = h0;
                acc[mt][nt][h * 2 + 1] = h1;
                s1 += h0 + h1;
                s2 += h0 * h0 + h1 * h1;
            }
            s1 += __shfl_xor_sync(0xffffffffu, s1, 1);
            s1 += __shfl_xor_sync(0xffffffffu, s1, 2);
            s2 += __shfl_xor_sync(0xffffffffu, s2, 1);
            s2 += __shfl_xor_sync(0xffffffffu, s2, 2);
            scr[r * 4 + wn] = s1;
            scr[512 + r * 4 + wn] = s2;
        }
    __syncthreads();
    float* ob = out + (size_t)b * (NF * CC);
#pragma unroll
    for (int mt = 0; mt < 2; mt++)
#pragma unroll
        for (int h = 0; h < 2; h++) {
            const int r = mrow + mt * 16 + g + h * 8;
            const float S  = scr[r * 4] + scr[r * 4 + 1] + scr[r * 4 + 2] + scr[r * 4 + 3];
            const float Q2 = scr[512 + r * 4] + scr[512 + r * 4 + 1]
                           + scr[512 + r * 4 + 2] + scr[512 + r * 4 + 3];
            const float mean = S * (1.f / 256.f);
            const float rstd = rsqrtf(Q2 * (1.f / 256.f) - mean * mean + 1e-5f);
#pragma unroll
            for (int nt = 0; nt < 8; nt++) {
                const int n = ncol + nt * 8 + 2 * t;
                float2 g2 = __ldg((const float2*)&gamma[n]);
                float2 b2 = __ldg((const float2*)&beta[n]);
                float2 o;
                o.x = (acc[mt][nt][h * 2 + 0] - mean) * rstd * g2.x + b2.x;
                o.y = (acc[mt][nt][h * 2 + 1] - mean) * rstd * g2.y + b2.y;
                *(float2*)(ob + r * 256 + n) = o;
            }
        }
#undef ISSUE_W2
#undef ZACC
}

extern "C" void kernel_launch(void* const* d_in, const int* in_sizes, int n_in,
                              void* d_out, int out_size)
{
    (void)in_sizes; (void)n_in; (void)out_size;
    const float* x     = (const float*)d_in[0];
    const float* ee    = (const float*)d_in[1];
    const float* adj   = (const float*)d_in[2];
    const float* alpha = (const float*)d_in[3];
    const float* Wq    = (const float*)d_in[4];
    const float* bq    = (const float*)d_in[5];
    const float* Wk    = (const float*)d_in[6];
    const float* bk    = (const float*)d_in[7];
    const float* Wv    = (const float*)d_in[8];
    const float* bv    = (const float*)d_in[9];
    const float* Wg    = (const float*)d_in[10];
    const float* bg    = (const float*)d_in[11];
    const float* gamma = (const float*)d_in[12];
    const float* beta  = (const float*)d_in[13];
    float* out = (float*)d_out;

    cudaFuncSetAttribute(fused_kernel, cudaFuncAttributeMaxDynamicSharedMemorySize, SMEM_BYTES);
    prep_all<<<64, 256>>>(Wq, Wk, Wg, Wv, bv, bg);
    prep_eqk<<<128, 256>>>(ee, Wq, Wk, bq, bk);
    fused_kernel<<<BT, 512, SMEM_BYTES>>>(x, adj, alpha, gamma, beta, out);
}

// round 17
// speedup vs baseline: 1.1988x; 1.1988x over previous
#include <cuda_runtime.h>
#include <cuda_fp16.h>
#include <cstdint>

#define BT 2048
#define NF 128
#define CC 256

// Device globals (no allocations)
__device__ uint32_t g_WqkPh[CC * CC / 2];    // pair-interleaved half2 B: n<128 Wq, else Wk
__device__ uint32_t g_WctPh[CC * CC / 2];    // pair-interleaved half2 B: Wc = Wg@Wv
__device__ float    g_bc[CC];                // Wg @ bv + bg

__device__ __forceinline__ uint32_t pk(float a, float b) {
    __half2 h = __floats2half2_rn(a, b);
    return *(uint32_t*)&h;
}
__device__ __forceinline__ uint32_t smem_u32(const void* p) {
    uint32_t a;
    asm("{ .reg .u64 t; cvta.to.shared.u64 t, %1; cvt.u32.u64 %0, t; }" : "=r"(a) : "l"(p));
    return a;
}
#define CP16(d, s) asm volatile("cp.async.ca.shared.global [%0], [%1], 16;" :: "r"(d), "l"(s) : "memory")
#define CP_COMMIT() asm volatile("cp.async.commit_group;" ::: "memory")
#define CP_WAIT2()  asm volatile("cp.async.wait_group 2;" ::: "memory")

__device__ __forceinline__ void mma16(float c[4], uint4 a, uint32_t b0, uint32_t b1) {
    asm volatile(
        "mma.sync.aligned.m16n8k16.row.col.f32.f16.f16.f32 "
        "{%0,%1,%2,%3},{%4,%5,%6,%7},{%8,%9},{%0,%1,%2,%3};"
        : "+f"(c[0]), "+f"(c[1]), "+f"(c[2]), "+f"(c[3])
        : "r"(a.x), "r"(a.y), "r"(a.z), "r"(a.w), "r"(b0), "r"(b1));
}

// Pair-interleaved B-pack word index: two adjacent 8-col fragments share a 16B slot.
// word = ((s*NP2 + gp2)*32 + g*4 + t)*4 + go*2 + hi   (NP2 = N/16)
__device__ __forceinline__ int bw2(int NP2, int k, int n) {
    int s = k >> 4, kk = k & 15, t = (kk & 7) >> 1, hi = kk >> 3;
    int gp = n >> 3, gp2 = gp >> 1, go = gp & 1, g = n & 7;
    return ((s * NP2 + gp2) * 32 + g * 4 + t) * 4 + go * 2 + hi;
}

// k16 step, uint2 B loads (legacy pack; phase 3)
template <int NT>
__device__ __forceinline__ void step16(float (&acc)[2][8][4], const uint32_t* __restrict__ Aw,
                                       const uint32_t* __restrict__ Bw) {
    uint4 af[2];
#pragma unroll
    for (int mt = 0; mt < 2; mt++) af[mt] = *(const uint4*)(Aw + mt * 128);
#pragma unroll
    for (int nt = 0; nt < NT; nt++) {
        uint2 bf = *(const uint2*)(Bw + nt * 64);
#pragma unroll
        for (int mt = 0; mt < 2; mt++) mma16(acc[mt][nt], af[mt], bf.x, bf.y);
    }
}
// k16 step, uint4 B loads (pair-interleaved pack; phases 1, 2, 4)
template <int NT2>
__device__ __forceinline__ void step16w(float (&acc)[2][8][4], const uint32_t* __restrict__ Aw,
                                        const uint32_t* __restrict__ Bw) {
    uint4 af[2];
#pragma unroll
    for (int mt = 0; mt < 2; mt++) af[mt] = *(const uint4*)(Aw + mt * 128);
#pragma unroll
    for (int nt2 = 0; nt2 < NT2; nt2++) {
        uint4 bf = *(const uint4*)(Bw + nt2 * 128);
#pragma unroll
        for (int mt = 0; mt < 2; mt++) {
            mma16(acc[mt][2 * nt2],     af[mt], bf.x, bf.y);
            mma16(acc[mt][2 * nt2 + 1], af[mt], bf.z, bf.w);
        }
    }
}

// ---------------- merged prep: 64 blocks x 4 Wct rows, pair-interleaved packs ----------------
__global__ void prep_all(const float* __restrict__ Wq, const float* __restrict__ Wk,
                         const float* __restrict__ Wg, const float* __restrict__ Wv,
                         const float* __restrict__ bv, const float* __restrict__ bg)
{
    __shared__ float sWg[4][256];
    __shared__ float sWct[4][260];
    __shared__ float part[4][8];
    const int bi = blockIdx.x;
    const int j = threadIdx.x;
    const int i0 = bi * 4;
    const int w8 = j >> 5, lane = j & 31;

#pragma unroll
    for (int r = 0; r < 4; r++) sWg[r][j] = Wg[(i0 + r) * 256 + j];
    __syncthreads();

    float acc[4] = {0.f, 0.f, 0.f, 0.f};
#pragma unroll 4
    for (int k = 0; k < 256; k++) {
        float wv = Wv[k * 256 + j];
#pragma unroll
        for (int r = 0; r < 4; r++) acc[r] = fmaf(sWg[r][k], wv, acc[r]);
    }
#pragma unroll
    for (int r = 0; r < 4; r++) sWct[r][j] = acc[r];

#pragma unroll
    for (int r = 0; r < 4; r++) {
        float v = sWg[r][j] * bv[j];
#pragma unroll
        for (int off = 16; off; off >>= 1) v += __shfl_xor_sync(0xffffffffu, v, off);
        if (lane == 0) part[r][w8] = v;
    }
    __syncthreads();

    if (j < 4) {
        float s = 0.f;
#pragma unroll
        for (int ww = 0; ww < 8; ww++) s += part[j][ww];
        g_bc[i0 + j] = s + bg[i0 + j];
    }
#pragma unroll
    for (int q = 0; q < 2; q++) {
        int idx = j * 2 + q;
        int nl = idx >> 7, kp = idx & 127;
        g_WctPh[bw2(16, 2 * kp, i0 + nl)] = pk(sWct[nl][2 * kp], sWct[nl][2 * kp + 1]);
    }
#pragma unroll
    for (int q = 0; q < 2; q++) {
        int p2 = bi * 512 + j * 2 + q;
        int kp = p2 >> 8, n = p2 & 255;
        float q0, q1;
        if (n < 128) { q0 = Wq[n * 256 + 2 * kp]; q1 = Wq[n * 256 + 2 * kp + 1]; }
        else         { q0 = Wk[(n - 128) * 256 + 2 * kp]; q1 = Wk[(n - 128) * 256 + 2 * kp + 1]; }
        g_WqkPh[bw2(16, 2 * kp, n)] = pk(q0, q1);
    }
}

// SMEM word map: scr[1024] | A1[16384] (xe -> Q|Kt -> attn|Kt -> ax) | BB[16384]
constexpr int OFF_SCR = 0;
constexpr int OFF_A   = 1024;
constexpr int OFF_BB  = OFF_A + 16384;
constexpr int SMEM_W  = OFF_BB + 16384;      // 33792 words
constexpr int SMEM_BYTES = SMEM_W * 4;       // 135168 B

__global__ void __launch_bounds__(512, 1)
fused_kernel(const float* __restrict__ x, const float* __restrict__ ee,
             const float* __restrict__ adj, const float* __restrict__ alpha_p,
             const float* __restrict__ bq, const float* __restrict__ bk,
             const float* __restrict__ gamma, const float* __restrict__ beta,
             float* __restrict__ out)
{
    extern __shared__ uint32_t smw[];
    float*    scr = (float*)(smw + OFF_SCR);
    uint32_t* A1  = smw + OFF_A;
    uint32_t* BB  = smw + OFF_BB;
    const uint32_t bbu = smem_u32(smw + OFF_BB);

    const int tid = threadIdx.x;
    const int w = tid >> 5, lane = tid & 31;
    const int g = lane >> 2, t = lane & 3;
    const int wm = w >> 2, wn = w & 3;          // 4 x 4 warp grid
    const int mrow = wm * 32;
    const int ncol = wn * 64;                   // phases 1,3,4 (N=256)
    const int ncol2 = wn * 32;                  // phase 2 (N=128)
    const int b = blockIdx.x;
    const float* xb = x + (size_t)b * (NF * CC);

    float acc[2][8][4];

#define ISSUE_W2(cc, gW) do { \
    if ((cc) < 8) { \
        uint32_t d = bbu + (((cc) & 3) * 4096 + tid * 8) * 4; \
        const uint32_t* s_ = (gW) + (cc) * 4096 + tid * 8; \
        CP16(d, s_); CP16(d + 16, s_ + 4); \
    } \
    CP_COMMIT(); \
} while (0)

#define ZACC() do { \
    _Pragma("unroll") for (int mt = 0; mt < 2; mt++) \
    _Pragma("unroll") for (int nt = 0; nt < 8; nt++) \
    _Pragma("unroll") for (int e = 0; e < 4; e++) acc[mt][nt][e] = 0.f; \
} while (0)

    ISSUE_W2(0, g_WqkPh);
    ISSUE_W2(1, g_WqkPh);

    // ===== stage xe = fp16(x+ee), fragment-owner conflict-free uint4 =====
#pragma unroll
    for (int it = 0; it < 8; it++) {
        int u = it * 16 + w;
        int slab = u >> 5, s = (u >> 1) & 15, mt = u & 1;
        int r0 = slab * 32 + mt * 16 + g;
        int k0 = s * 16 + 2 * t;
        const float* px = xb + r0 * 256 + k0;
        const float* pe = ee + r0 * 256 + k0;
        float2 a0 = __ldg((const float2*)px);
        float2 a1 = __ldg((const float2*)(px + 8 * 256));
        float2 a2 = __ldg((const float2*)(px + 8));
        float2 a3 = __ldg((const float2*)(px + 8 * 256 + 8));
        float2 e0 = __ldg((const float2*)pe);
        float2 e1 = __ldg((const float2*)(pe + 8 * 256));
        float2 e2 = __ldg((const float2*)(pe + 8));
        float2 e3 = __ldg((const float2*)(pe + 8 * 256 + 8));
        uint4 v;
        v.x = pk(a0.x + e0.x, a0.y + e0.y);
        v.y = pk(a1.x + e1.x, a1.y + e1.y);
        v.z = pk(a2.x + e2.x, a2.y + e2.y);
        v.w = pk(a3.x + e3.x, a3.y + e3.y);
        ((uint4*)A1)[((slab * 16 + s) * 2 + mt) * 32 + lane] = v;
    }

    // ===== Phase 1: [Q|K] = xe @ Wqk^T  (8 double-ksteps, uint4 B) =====
    ZACC();
    for (int cc = 0; cc < 8; cc++) {
        ISSUE_W2(cc + 2, g_WqkPh);
        CP_WAIT2();
        __syncthreads();
#pragma unroll
        for (int sl = 0; sl < 2; sl++)
            step16w<4>(acc, A1 + wm * 4096 + (2 * cc + sl) * 256 + lane * 4,
                       BB + (cc & 3) * 4096 + sl * 2048 + wn * 512 + lane * 4);
    }
    __syncthreads();   // all xe reads done before Q/Kt overwrite A1

    // epilogue: Q-pack (wn<2) uint4 / Kt-pack (wn>=2) pair-interleaved uint4
    if (wn < 2) {
#pragma unroll
        for (int np = 0; np < 4; np++) {
            int n0 = ncol + np * 16 + 2 * t;
            float2 b0 = __ldg((const float2*)&bq[n0]);
            float2 b1 = __ldg((const float2*)&bq[n0 + 8]);
#pragma unroll
            for (int mt = 0; mt < 2; mt++) {
                uint4 v;
                v.x = pk(acc[mt][2 * np][0] + b0.x, acc[mt][2 * np][1] + b0.y);
                v.y = pk(acc[mt][2 * np][2] + b0.x, acc[mt][2 * np][3] + b0.y);
                v.z = pk(acc[mt][2 * np + 1][0] + b1.x, acc[mt][2 * np + 1][1] + b1.y);
                v.w = pk(acc[mt][2 * np + 1][2] + b1.x, acc[mt][2 * np + 1][3] + b1.y);
                ((uint4*)A1)[((wm * 8 + wn * 4 + np) * 2 + mt) * 32 + lane] = v;
            }
        }
    } else {
#pragma unroll
        for (int np = 0; np < 4; np++) {
            int ck0 = (wn - 2) * 64 + np * 16 + 2 * t;
            int sb = (wn - 2) * 4 + np;
            float2 b0 = __ldg((const float2*)&bk[ck0]);
            float2 b1 = __ldg((const float2*)&bk[ck0 + 8]);
#pragma unroll
            for (int mt = 0; mt < 2; mt++) {
                uint4 v;
                v.x = pk(acc[mt][2 * np][0] + b0.x, acc[mt][2 * np][1] + b0.y);
                v.y = pk(acc[mt][2 * np + 1][0] + b1.x, acc[mt][2 * np + 1][1] + b1.y);
                v.z = pk(acc[mt][2 * np][2] + b0.x, acc[mt][2 * np][3] + b0.y);
                v.w = pk(acc[mt][2 * np + 1][2] + b1.x, acc[mt][2 * np + 1][3] + b1.y);
                ((uint4*)(A1 + 8192))[(sb * 8 + wm * 2 + mt) * 32 + lane] = v;
            }
        }
    }
    __syncthreads();

    // ===== Phase 2: scores = Q @ K^T  (8 ksteps, uint4 B from pair-interleaved Kt) =====
    ZACC();
#pragma unroll
    for (int s = 0; s < 8; s++)
        step16w<2>(acc, A1 + wm * 2048 + s * 256 + lane * 4,
                   A1 + 8192 + s * 1024 + wn * 256 + lane * 4);

    // ===== softmax (no max pass) -> attn-pack uint4 =====
    {
        const float fa = __ldg(alpha_p);
        const float invs = 0.08838834764831845f;
#pragma unroll
        for (int mt = 0; mt < 2; mt++)
#pragma unroll
            for (int h = 0; h < 2; h++) {
                const int r = mrow + mt * 16 + g + h * 8;
                float s = 0.f;
#pragma unroll
                for (int nt = 0; nt < 4; nt++) {
                    const int col = ncol2 + nt * 8 + 2 * t;
                    float2 av = __ldg((const float2*)&adj[r * 128 + col]);
                    float p0 = __expf(acc[mt][nt][h * 2 + 0] * invs + fa * fmaxf(av.x, 0.f));
                    float p1 = __expf(acc[mt][nt][h * 2 + 1] * invs + fa * fmaxf(av.y, 0.f));
                    acc[mt][nt][h * 2 + 0] = p0;
                    acc[mt][nt][h * 2 + 1] = p1;
                    s += p0 + p1;
                }
                s += __shfl_xor_sync(0xffffffffu, s, 1);
                s += __shfl_xor_sync(0xffffffffu, s, 2);
                scr[r * 4 + wn] = s;
            }
        __syncthreads();
#pragma unroll
        for (int mt = 0; mt < 2; mt++) {
            const int r0 = mrow + mt * 16 + g;
            const float* s0 = &scr[r0 * 4];
            const float* s1 = &scr[(r0 + 8) * 4];
            const float inv0 = 1.f / (s0[0] + s0[1] + s0[2] + s0[3]);
            const float inv1 = 1.f / (s1[0] + s1[1] + s1[2] + s1[3]);
#pragma unroll
            for (int np = 0; np < 2; np++) {
                uint4 v;
                v.x = pk(acc[mt][2 * np][0] * inv0, acc[mt][2 * np][1] * inv0);
                v.y = pk(acc[mt][2 * np][2] * inv1, acc[mt][2 * np][3] * inv1);
                v.z = pk(acc[mt][2 * np + 1][0] * inv0, acc[mt][2 * np + 1][1] * inv0);
                v.w = pk(acc[mt][2 * np + 1][2] * inv1, acc[mt][2 * np + 1][3] * inv1);
                ((uint4*)A1)[((wm * 8 + wn * 2 + np) * 2 + mt) * 32 + lane] = v;
            }
        }
    }
    __syncthreads();   // attn visible before phase-3 reads

    // ===== Phase 3: ax = attn @ x  (4 chunks, fragment-owner staging, uint2 B) =====
#define STAGE_X3(cidx, buf) do { \
    const float* xs_ = xb + (cidx) * 32 * 256; \
    _Pragma("unroll") \
    for (int it = 0; it < 4; it++) { \
        int u = it * 16 + w; \
        int sl = u >> 5, gp = u & 31; \
        int n_ = gp * 8 + (lane >> 2); \
        const float* p0 = xs_ + (sl * 16 + 2 * (lane & 3)) * 256 + n_; \
        float v0 = __ldg(p0), v1 = __ldg(p0 + 256); \
        float v8 = __ldg(p0 + 8 * 256), v9 = __ldg(p0 + 9 * 256); \
        uint2 vv; vv.x = pk(v0, v1); vv.y = pk(v8, v9); \
        ((uint2*)(buf))[(sl * 32 + gp) * 32 + lane] = vv; \
    } \
} while (0)

    ZACC();
    STAGE_X3(0, BB);
    __syncthreads();
    for (int c = 0; c < 4; c++) {
        if (c < 3) STAGE_X3(c + 1, BB + ((c + 1) & 1) * 4096);
        uint32_t* cur = BB + (c & 1) * 4096;
#pragma unroll
        for (int sl = 0; sl < 2; sl++)
            step16<8>(acc, A1 + wm * 2048 + (c * 2 + sl) * 256 + lane * 4,
                      cur + sl * 2048 + wn * 512 + lane * 2);
        __syncthreads();
    }

    // prefetch first two weight double-chunks of phase 4
    ISSUE_W2(0, g_WctPh);
    ISSUE_W2(1, g_WctPh);

    // epilogue: ax-pack (S=16) uint4, conflict-free (attn/Kt dead)
#pragma unroll
    for (int np = 0; np < 4; np++)
#pragma unroll
        for (int mt = 0; mt < 2; mt++) {
            uint4 v;
            v.x = pk(acc[mt][2 * np][0], acc[mt][2 * np][1]);
            v.y = pk(acc[mt][2 * np][2], acc[mt][2 * np][3]);
            v.z = pk(acc[mt][2 * np + 1][0], acc[mt][2 * np + 1][1]);
            v.w = pk(acc[mt][2 * np + 1][2], acc[mt][2 * np + 1][3]);
            ((uint4*)A1)[((wm * 16 + wn * 4 + np) * 2 + mt) * 32 + lane] = v;
        }
    __syncthreads();

    // ===== Phase 4: z = ax @ Wc^T  (8 double-ksteps, uint4 B) =====
    ZACC();
    for (int cc = 0; cc < 8; cc++) {
        ISSUE_W2(cc + 2, g_WctPh);
        CP_WAIT2();
        __syncthreads();
#pragma unroll
        for (int sl = 0; sl < 2; sl++)
            step16w<4>(acc, A1 + wm * 4096 + (2 * cc + sl) * 256 + lane * 4,
                       BB + (cc & 3) * 4096 + sl * 2048 + wn * 512 + lane * 4);
    }

    // ===== LN epilogue: h = relu(z + bc) + x; LayerNorm over C; store =====
#pragma unroll
    for (int mt = 0; mt < 2; mt++)
#pragma unroll
        for (int h = 0; h < 2; h++) {
            const int r = mrow + mt * 16 + g + h * 8;
            float s1 = 0.f, s2 = 0.f;
#pragma unroll
            for (int nt = 0; nt < 8; nt++) {
                const int n = ncol + nt * 8 + 2 * t;
                float2 bc2 = __ldg((const float2*)&g_bc[n]);
                float2 xv = __ldg((const float2*)&xb[r * 256 + n]);
                float h0 = fmaxf(acc[mt][nt][h * 2 + 0] + bc2.x, 0.f) + xv.x;
                float h1 = fmaxf(acc[mt][nt][h * 2 + 1] + bc2.y, 0.f) + xv.y;
                acc[mt][nt][h * 2 + 0] = h0;
                acc[mt][nt][h * 2 + 1] = h1;
                s1 += h0 + h1;
                s2 += h0 * h0 + h1 * h1;
            }
            s1 += __shfl_xor_sync(0xffffffffu, s1, 1);
            s1 += __shfl_xor_sync(0xffffffffu, s1, 2);
            s2 += __shfl_xor_sync(0xffffffffu, s2, 1);
            s2 += __shfl_xor_sync(0xffffffffu, s2, 2);
            scr[r * 4 + wn] = s1;
            scr[512 + r * 4 + wn] = s2;
        }
    __syncthreads();
    float* ob = out + (size_t)b * (NF * CC);
#pragma unroll
    for (int mt = 0; mt < 2; mt++)
#pragma unroll
        for (int h = 0; h < 2; h++) {
            const int r = mrow + mt * 16 + g + h * 8;
            const float S  = scr[r * 4] + scr[r * 4 + 1] + scr[r * 4 + 2] + scr[r * 4 + 3];
            const float Q2 = scr[512 + r * 4] + scr[512 + r * 4 + 1]
                           + scr[512 + r * 4 + 2] + scr[512 + r * 4 + 3];
            const float mean = S * (1.f / 256.f);
            const float rstd = rsqrtf(Q2 * (1.f / 256.f) - mean * mean + 1e-5f);
#pragma unroll
            for (int nt = 0; nt < 8; nt++) {
                const int n = ncol + nt * 8 + 2 * t;
                float2 g2 = __ldg((const float2*)&gamma[n]);
                float2 b2 = __ldg((const float2*)&beta[n]);
                float2 o;
                o.x = (acc[mt][nt][h * 2 + 0] - mean) * rstd * g2.x + b2.x;
                o.y = (acc[mt][nt][h * 2 + 1] - mean) * rstd * g2.y + b2.y;
                *(float2*)(ob + r * 256 + n) = o;
            }
        }
#undef ISSUE_W2
#undef ZACC
#undef STAGE_X3
}

extern "C" void kernel_launch(void* const* d_in, const int* in_sizes, int n_in,
                              void* d_out, int out_size)
{
    (void)in_sizes; (void)n_in; (void)out_size;
    const float* x     = (const float*)d_in[0];
    const float* ee    = (const float*)d_in[1];
    const float* adj   = (const float*)d_in[2];
    const float* alpha = (const float*)d_in[3];
    const float* Wq    = (const float*)d_in[4];
    const float* bq    = (const float*)d_in[5];
    const float* Wk    = (const float*)d_in[6];
    const float* bk    = (const float*)d_in[7];
    const float* Wv    = (const float*)d_in[8];
    const float* bv    = (const float*)d_in[9];
    const float* Wg    = (const float*)d_in[10];
    const float* bg    = (const float*)d_in[11];
    const float* gamma = (const float*)d_in[12];
    const float* beta  = (const float*)d_in[13];
    float* out = (float*)d_out;

    cudaFuncSetAttribute(fused_kernel, cudaFuncAttributeMaxDynamicSharedMemorySize, SMEM_BYTES);
    prep_all<<<64, 256>>>(Wq, Wk, Wg, Wv, bv, bg);
    fused_kernel<<<BT, 512, SMEM_BYTES>>>(x, ee, adj, alpha, bq, bk, gamma, beta, out);
}